// round 1
// baseline (speedup 1.0000x reference)
#include <cuda_runtime.h>
#include <cuda_bf16.h>
#include <cstdint>

// Problem constants (B,H,S,D) = (8,8,2048,64)
#define PB 8
#define PH 8
#define PS 2048
#define PD 64
#define INV_T 0.125f

constexpr int TILE_M = 64;   // i-rows per CTA
constexpr int TILE_N = 64;   // j-cols per iteration
constexpr int SMS    = 68;   // smem row stride in words (64 + 4 pad -> conflict-free frag loads)
constexpr int SMEM_BYTES = 3 * TILE_M * SMS * 4;  // sQ/sP, sK, sV

__device__ __forceinline__ uint32_t f2tf32(float f) {
    uint32_t r;
    asm("cvt.rna.tf32.f32 %0, %1;" : "=r"(r) : "f"(f));
    return r;
}

__device__ __forceinline__ void mma_tf32(float c[4], const uint32_t a[4], const uint32_t b[2]) {
    asm volatile(
        "mma.sync.aligned.m16n8k8.row.col.f32.tf32.tf32.f32 "
        "{%0,%1,%2,%3}, {%4,%5,%6,%7}, {%8,%9}, {%0,%1,%2,%3};"
        : "+f"(c[0]), "+f"(c[1]), "+f"(c[2]), "+f"(c[3])
        : "r"(a[0]), "r"(a[1]), "r"(a[2]), "r"(a[3]),
          "r"(b[0]), "r"(b[1]));
}

__global__ __launch_bounds__(128)
void attn_tf32_kernel(const float* __restrict__ q,
                      const float* __restrict__ k,
                      const float* __restrict__ v,
                      const float* __restrict__ pos,
                      const float* __restrict__ mask,
                      float* __restrict__ out)
{
    extern __shared__ uint32_t smem[];
    uint32_t* sQ = smem;                    // reused as P tile after Q frags cached
    uint32_t* sK = smem + TILE_M * SMS;
    uint32_t* sV = smem + 2 * TILE_M * SMS;

    const int bx   = blockIdx.x;            // itile*8 + b  (consecutive blocks share itile, same h)
    const int h    = blockIdx.y;
    const int b    = bx & 7;
    const int i0   = (bx >> 3) * TILE_M;
    const int tid  = threadIdx.x;
    const int warp = tid >> 5;
    const int lane = tid & 31;
    const int tg   = lane >> 2;              // groupID   (0..7)
    const int tc   = lane & 3;               // thread-in-group (0..3)

    const size_t bh = (size_t)(b * PH + h);
    const float* qb   = q   + bh * (size_t)PS * PD;
    const float* kb   = k   + bh * (size_t)PS * PD;
    const float* vb   = v   + bh * (size_t)PS * PD;
    const float* posb = pos + (size_t)h * PS * PS;
    float*       ob   = out + bh * (size_t)PS * PD;

    // ---- Stage Q tile (64x64) into smem as tf32 ----
    #pragma unroll
    for (int p = 0; p < 8; ++p) {
        int idx = p * 128 + tid;
        int r = idx >> 4, c4 = idx & 15;
        float4 f = *(const float4*)(qb + (size_t)(i0 + r) * PD + c4 * 4);
        uint32_t* d = &sQ[r * SMS + c4 * 4];
        d[0] = f2tf32(f.x); d[1] = f2tf32(f.y); d[2] = f2tf32(f.z); d[3] = f2tf32(f.w);
    }
    __syncthreads();

    // ---- Cache Q A-fragments in registers (8 k-steps x 4 regs) ----
    uint32_t qa[8][4];
    {
        const uint32_t* base = sQ + warp * 16 * SMS;
        #pragma unroll
        for (int ks = 0; ks < 8; ++ks) {
            int c0 = ks * 8 + tc;
            qa[ks][0] = base[tg * SMS + c0];
            qa[ks][1] = base[(tg + 8) * SMS + c0];
            qa[ks][2] = base[tg * SMS + c0 + 4];
            qa[ks][3] = base[(tg + 8) * SMS + c0 + 4];
        }
    }
    // sQ's per-warp 16-row region now free for this warp's P tile (no cross-warp use).

    const int irow0 = i0 + warp * 16 + tg;
    const int irow1 = irow0 + 8;

    float m_i[2] = {-1e30f, -1e30f};
    float l_i[2] = {0.f, 0.f};
    float o[8][4];
    #pragma unroll
    for (int n = 0; n < 8; ++n) { o[n][0] = o[n][1] = o[n][2] = o[n][3] = 0.f; }

    for (int j0 = 0; j0 < PS; j0 += TILE_N) {
        __syncthreads();   // protect sK/sV vs previous iteration readers
        // ---- Stage K and V tiles (64x64 each) as tf32 ----
        #pragma unroll
        for (int p = 0; p < 8; ++p) {
            int idx = p * 128 + tid;
            int r = idx >> 4, c4 = idx & 15;
            float4 fk = *(const float4*)(kb + (size_t)(j0 + r) * PD + c4 * 4);
            float4 fv = *(const float4*)(vb + (size_t)(j0 + r) * PD + c4 * 4);
            uint32_t* dk = &sK[r * SMS + c4 * 4];
            dk[0] = f2tf32(fk.x); dk[1] = f2tf32(fk.y); dk[2] = f2tf32(fk.z); dk[3] = f2tf32(fk.w);
            uint32_t* dv = &sV[r * SMS + c4 * 4];
            dv[0] = f2tf32(fv.x); dv[1] = f2tf32(fv.y); dv[2] = f2tf32(fv.z); dv[3] = f2tf32(fv.w);
        }
        __syncthreads();

        // ---- S = Q K^T  (m16 x n64 per warp) ----
        float c[8][4];
        #pragma unroll
        for (int n = 0; n < 8; ++n) { c[n][0] = c[n][1] = c[n][2] = c[n][3] = 0.f; }
        #pragma unroll
        for (int ks = 0; ks < 8; ++ks) {
            #pragma unroll
            for (int n = 0; n < 8; ++n) {
                uint32_t bf[2];
                bf[0] = sK[(n * 8 + tg) * SMS + ks * 8 + tc];
                bf[1] = sK[(n * 8 + tg) * SMS + ks * 8 + tc + 4];
                mma_tf32(c[n], qa[ks], bf);
            }
        }

        // ---- sim = mask * (s * invT + pos); track row max ----
        float mnew0 = m_i[0], mnew1 = m_i[1];
        #pragma unroll
        for (int n = 0; n < 8; ++n) {
            int jc = j0 + n * 8 + tc * 2;
            float2 p0  = *(const float2*)(posb + (size_t)irow0 * PS + jc);
            float2 p1  = *(const float2*)(posb + (size_t)irow1 * PS + jc);
            float2 mk0 = *(const float2*)(mask + (size_t)irow0 * PS + jc);
            float2 mk1 = *(const float2*)(mask + (size_t)irow1 * PS + jc);
            c[n][0] = mk0.x * (c[n][0] * INV_T + p0.x);
            c[n][1] = mk0.y * (c[n][1] * INV_T + p0.y);
            c[n][2] = mk1.x * (c[n][2] * INV_T + p1.x);
            c[n][3] = mk1.y * (c[n][3] * INV_T + p1.y);
            mnew0 = fmaxf(mnew0, fmaxf(c[n][0], c[n][1]));
            mnew1 = fmaxf(mnew1, fmaxf(c[n][2], c[n][3]));
        }
        mnew0 = fmaxf(mnew0, __shfl_xor_sync(0xffffffffu, mnew0, 1));
        mnew0 = fmaxf(mnew0, __shfl_xor_sync(0xffffffffu, mnew0, 2));
        mnew1 = fmaxf(mnew1, __shfl_xor_sync(0xffffffffu, mnew1, 1));
        mnew1 = fmaxf(mnew1, __shfl_xor_sync(0xffffffffu, mnew1, 2));

        float alpha0 = __expf(m_i[0] - mnew0);
        float alpha1 = __expf(m_i[1] - mnew1);
        m_i[0] = mnew0; m_i[1] = mnew1;

        float rs0 = 0.f, rs1 = 0.f;
        #pragma unroll
        for (int n = 0; n < 8; ++n) {
            c[n][0] = __expf(c[n][0] - mnew0);
            c[n][1] = __expf(c[n][1] - mnew0);
            c[n][2] = __expf(c[n][2] - mnew1);
            c[n][3] = __expf(c[n][3] - mnew1);
            rs0 += c[n][0] + c[n][1];
            rs1 += c[n][2] + c[n][3];
        }
        rs0 += __shfl_xor_sync(0xffffffffu, rs0, 1);
        rs0 += __shfl_xor_sync(0xffffffffu, rs0, 2);
        rs1 += __shfl_xor_sync(0xffffffffu, rs1, 1);
        rs1 += __shfl_xor_sync(0xffffffffu, rs1, 2);

        l_i[0] = l_i[0] * alpha0 + rs0;
        l_i[1] = l_i[1] * alpha1 + rs1;
        #pragma unroll
        for (int n = 0; n < 8; ++n) {
            o[n][0] *= alpha0; o[n][1] *= alpha0;
            o[n][2] *= alpha1; o[n][3] *= alpha1;
        }

        // ---- store P (tf32) into this warp's region of sQ ----
        uint32_t* sP = sQ + warp * 16 * SMS;
        #pragma unroll
        for (int n = 0; n < 8; ++n) {
            int col = n * 8 + tc * 2;
            sP[tg * SMS + col]           = f2tf32(c[n][0]);
            sP[tg * SMS + col + 1]       = f2tf32(c[n][1]);
            sP[(tg + 8) * SMS + col]     = f2tf32(c[n][2]);
            sP[(tg + 8) * SMS + col + 1] = f2tf32(c[n][3]);
        }
        __syncwarp();

        // ---- O += P V  (k = j dimension, 8 steps) ----
        #pragma unroll
        for (int ks = 0; ks < 8; ++ks) {
            uint32_t pa[4];
            pa[0] = sP[tg * SMS + ks * 8 + tc];
            pa[1] = sP[(tg + 8) * SMS + ks * 8 + tc];
            pa[2] = sP[tg * SMS + ks * 8 + tc + 4];
            pa[3] = sP[(tg + 8) * SMS + ks * 8 + tc + 4];
            #pragma unroll
            for (int nd = 0; nd < 8; ++nd) {
                uint32_t bf[2];
                bf[0] = sV[(ks * 8 + tc) * SMS + nd * 8 + tg];
                bf[1] = sV[(ks * 8 + tc + 4) * SMS + nd * 8 + tg];
                mma_tf32(o[nd], pa, bf);
            }
        }
        __syncwarp();   // P reads done before next iteration's P writes
    }

    // ---- epilogue: normalize and write out ----
    float inv0 = 1.f / l_i[0];
    float inv1 = 1.f / l_i[1];
    #pragma unroll
    for (int nd = 0; nd < 8; ++nd) {
        float2 w0 = make_float2(o[nd][0] * inv0, o[nd][1] * inv0);
        float2 w1 = make_float2(o[nd][2] * inv1, o[nd][3] * inv1);
        *(float2*)(ob + (size_t)irow0 * PD + nd * 8 + tc * 2) = w0;
        *(float2*)(ob + (size_t)irow1 * PD + nd * 8 + tc * 2) = w1;
    }
}

extern "C" void kernel_launch(void* const* d_in, const int* in_sizes, int n_in,
                              void* d_out, int out_size)
{
    const float* q    = (const float*)d_in[0];
    const float* k    = (const float*)d_in[1];
    const float* v    = (const float*)d_in[2];
    const float* pos  = (const float*)d_in[3];
    const float* mask = (const float*)d_in[4];
    float* out = (float*)d_out;

    static bool attr_set = false;
    if (!attr_set) {
        cudaFuncSetAttribute(attn_tf32_kernel,
                             cudaFuncAttributeMaxDynamicSharedMemorySize, SMEM_BYTES);
        attr_set = true;
    }

    dim3 grid((PS / TILE_M) * PB, PH);   // x: itile*8+b (consecutive share itile & h), y: h
    attn_tf32_kernel<<<grid, 128, SMEM_BYTES>>>(q, k, v, pos, mask, out);
}